// round 8
// baseline (speedup 1.0000x reference)
#include <cuda_runtime.h>
#include <cuda_fp16.h>
#include <cstdint>

#define NB 8
#define NN 2048
#define DF 128
#define NF 128

// ---------------- scratch (device globals; no allocation allowed) ----------
__device__ float  g_colsum[NB * NN];
__device__ float  g_d[NB * NN];
__device__ __half g_Xh[NB * NN * DF];   // split-hi of Xs = d*X, natural [b][j][f]
__device__ __half g_Xl[NB * NN * DF];   // split-lo
__device__ float  g_Y[NB * NN * NF];

// ---------------- helpers ---------------------------------------------------
__device__ __forceinline__ uint32_t smem_u32(const void* p) {
    uint32_t a;
    asm("{ .reg .u64 t; cvta.to.shared.u64 t, %1; cvt.u32.u64 %0, t; }"
        : "=r"(a) : "l"(p));
    return a;
}
__device__ __forceinline__ void ldmatrix_x4(uint32_t* r, uint32_t addr) {
    asm volatile("ldmatrix.sync.aligned.m8n8.x4.shared.b16 {%0,%1,%2,%3}, [%4];"
                 : "=r"(r[0]), "=r"(r[1]), "=r"(r[2]), "=r"(r[3]) : "r"(addr));
}
__device__ __forceinline__ void ldmatrix_x4_trans(uint32_t* r, uint32_t addr) {
    asm volatile("ldmatrix.sync.aligned.m8n8.x4.trans.shared.b16 {%0,%1,%2,%3}, [%4];"
                 : "=r"(r[0]), "=r"(r[1]), "=r"(r[2]), "=r"(r[3]) : "r"(addr));
}
__device__ __forceinline__ void mma16816(float* d, const uint32_t* a, const uint32_t* b) {
    asm volatile(
        "mma.sync.aligned.m16n8k16.row.col.f32.f16.f16.f32 "
        "{%0,%1,%2,%3}, {%4,%5,%6,%7}, {%8,%9}, {%0,%1,%2,%3};"
        : "+f"(d[0]), "+f"(d[1]), "+f"(d[2]), "+f"(d[3])
        : "r"(a[0]), "r"(a[1]), "r"(a[2]), "r"(a[3]), "r"(b[0]), "r"(b[1]));
}
__device__ __forceinline__ void cp_async16(uint32_t saddr, const void* gaddr) {
    asm volatile("cp.async.cg.shared.global [%0], [%1], 16;"
                 :: "r"(saddr), "l"(gaddr) : "memory");
}
__device__ __forceinline__ void cp_commit() {
    asm volatile("cp.async.commit_group;" ::: "memory");
}
__device__ __forceinline__ void cp_wait0() {
    asm volatile("cp.async.wait_group 0;" ::: "memory");
}
__device__ __forceinline__ void split_f16(float v, uint16_t& hi, uint16_t& lo) {
    __half h = __float2half_rn(v);
    float hf = __half2float(h);
    __half l = __float2half_rn(v - hf);
    hi = __half_as_ushort(h);
    lo = __half_as_ushort(l);
}

// ---------------------------------------------------------------------------
// 1. zero colsum accumulator
// ---------------------------------------------------------------------------
__global__ void k_zero() {
    int i = blockIdx.x * blockDim.x + threadIdx.x;
    if (i < NB * NN) g_colsum[i] = 0.0f;
}

// ---------------------------------------------------------------------------
// 2. column sums only (A -> outA copy fused into k_mma)
// ---------------------------------------------------------------------------
__global__ __launch_bounds__(256) void k_colsum(const float* __restrict__ A) {
    int b  = blockIdx.z;
    int c4 = blockIdx.x * 256 + threadIdx.x;
    int r0 = blockIdx.y * 128;
    const float4* Ab = (const float4*)(A + (size_t)b * NN * NN) + c4;
    float4 s = make_float4(0.f, 0.f, 0.f, 0.f);
    #pragma unroll 4
    for (int r = 0; r < 128; r++) {
        float4 v = Ab[(size_t)(r0 + r) * (NN / 4)];
        s.x += v.x; s.y += v.y; s.z += v.z; s.w += v.w;
    }
    float* cs = &g_colsum[b * NN + c4 * 4];
    atomicAdd(cs + 0, s.x);
    atomicAdd(cs + 1, s.y);
    atomicAdd(cs + 2, s.z);
    atomicAdd(cs + 3, s.w);
}

// ---------------------------------------------------------------------------
// 3. d = rsqrt(colsum+1); Xs = d*X split to fp16 hi/lo (natural layout)
// ---------------------------------------------------------------------------
__global__ __launch_bounds__(256) void k_dscale(const float* __restrict__ X) {
    int q   = blockIdx.x * 256 + threadIdx.x;          // float4 index
    int row = q >> 5;                                  // 32 float4 per row
    float dv = rsqrtf(g_colsum[row] + 1.0f);
    if ((q & 31) == 0) g_d[row] = dv;
    float4 v = ((const float4*)X)[q];
    uint16_t h0,l0,h1,l1,h2,l2,h3,l3;
    split_f16(dv * v.x, h0, l0); split_f16(dv * v.y, h1, l1);
    split_f16(dv * v.z, h2, l2); split_f16(dv * v.w, h3, l3);
    uint2 hv = make_uint2(((uint32_t)h1 << 16) | h0, ((uint32_t)h3 << 16) | h2);
    uint2 lv = make_uint2(((uint32_t)l1 << 16) | l0, ((uint32_t)l3 << 16) | l2);
    *(uint2*)&g_Xh[q * 4] = hv;
    *(uint2*)&g_Xl[q * 4] = lv;
}

// ---------------------------------------------------------------------------
// 4. HMMA GEMM: 128x128 CTA tile, KT=64, 8 warps (2x4, each 64x32 via 4x4
//    frags), double-buffered smem, cp.async B loads, fused A->outA copy.
//    acc = Ah@Bh + Ah@Bl + Al@Bh; epilogue Y = d*(acc + Xs).
// ---------------------------------------------------------------------------
#define KT 64
#define MT 128
#define A_STR 72            // halves per A row (64+8 pad); 144B = 9x16B (odd) ok
#define B_STR 136           // halves per B row (128+8 pad); 272B = 17x16B (odd) ok
#define A_BYTES (MT * A_STR * 2)      // 18432 per matrix (hi or lo)
#define B_BYTES (KT * B_STR * 2)      // 17408 per matrix
#define BUF_BYTES (2 * A_BYTES + 2 * B_BYTES)  // 71680
#define DYN_SMEM (2 * BUF_BYTES)               // 143360

__global__ __launch_bounds__(256, 1) void k_mma(const float* __restrict__ A,
                                                float* __restrict__ outA,
                                                float* __restrict__ Y) {
    extern __shared__ char smem[];
    int tid  = threadIdx.x;
    int wid  = tid >> 5;
    int lane = tid & 31;
    int wm   = wid >> 2;        // 0..1 (64 rows each)
    int wn   = wid & 3;         // 0..3 (32 cols each)
    int b    = blockIdx.y;
    int m0   = blockIdx.x * MT;

    const float*  Ab  = A    + (size_t)b * NN * NN + (size_t)m0 * NN;
    float*        Ob  = outA + (size_t)b * NN * NN + (size_t)m0 * NN;
    const __half* BhG = g_Xh + (size_t)b * NN * DF;
    const __half* BlG = g_Xl + (size_t)b * NN * DF;

    float acc[4][4][4];
    #pragma unroll
    for (int i = 0; i < 4; i++)
        #pragma unroll
        for (int j = 0; j < 4; j++)
            #pragma unroll
            for (int c = 0; c < 4; c++) acc[i][j][c] = 0.0f;

    auto ah_p = [&](int buf) { return smem + buf * BUF_BYTES; };
    auto bh_p = [&](int buf) { return smem + buf * BUF_BYTES + 2 * A_BYTES; };

    // ---- B via cp.async: per matrix 1024 uint4s, 4/thread ----
    auto issue_b = [&](int t, int buf) {
        int k0 = t * KT;
        uint32_t bh = smem_u32(bh_p(buf));
        uint32_t bl = bh + B_BYTES;
        #pragma unroll
        for (int i = 0; i < 4; i++) {
            int q = tid + i * 256, row = q >> 4, u = q & 15;
            uint32_t off = (uint32_t)(row * B_STR + u * 8) * 2;
            const __half* gh = BhG + (size_t)(k0 + row) * DF + u * 8;
            const __half* gl = BlG + (size_t)(k0 + row) * DF + u * 8;
            cp_async16(bh + off, gh);
            cp_async16(bl + off, gl);
        }
        cp_commit();
    };
    // ---- A via registers (needs fp32->fp16 split); writethrough to outA ----
    // 2048 float4 per tile, 8/thread: q = tid + i*256, row=q>>4, c4=q&15
    auto load_a = [&](int t, float4* pa) {
        int k0 = t * KT;
        #pragma unroll
        for (int i = 0; i < 8; i++) {
            int q = tid + i * 256, row = q >> 4, c4 = q & 15;
            const float4* src = (const float4*)(Ab + (size_t)row * NN + k0 + c4 * 4);
            pa[i] = *src;
            *(float4*)(Ob + (size_t)row * NN + k0 + c4 * 4) = pa[i];
        }
    };
    auto store_a = [&](int buf, const float4* pa) {
        char* ah = ah_p(buf); char* al = ah + A_BYTES;
        #pragma unroll
        for (int i = 0; i < 8; i++) {
            int q = tid + i * 256, row = q >> 4, c4 = q & 15;
            uint16_t h0,l0,h1,l1,h2,l2,h3,l3;
            split_f16(pa[i].x, h0, l0); split_f16(pa[i].y, h1, l1);
            split_f16(pa[i].z, h2, l2); split_f16(pa[i].w, h3, l3);
            uint2 hv = make_uint2(((uint32_t)h1 << 16) | h0, ((uint32_t)h3 << 16) | h2);
            uint2 lv = make_uint2(((uint32_t)l1 << 16) | l0, ((uint32_t)l3 << 16) | l2);
            int off = (row * A_STR + c4 * 4) * 2;
            *(uint2*)(ah + off) = hv;
            *(uint2*)(al + off) = lv;
        }
    };

    {   // prologue: tile 0
        issue_b(0, 0);
        float4 pa[8];
        load_a(0, pa);
        store_a(0, pa);
        cp_wait0();
    }
    __syncthreads();

    const int NT = NN / KT;     // 32
    for (int t = 0; t < NT; t++) {
        int buf = t & 1;
        float4 pa[8];
        if (t + 1 < NT) {
            issue_b(t + 1, buf ^ 1);
            load_a(t + 1, pa);
        }

        // ---- compute on buf: 4 ks-steps of 16 ----
        uint32_t aBase = smem_u32(ah_p(buf));
        uint32_t bBase = smem_u32(bh_p(buf));
        #pragma unroll
        for (int ks = 0; ks < KT; ks += 16) {
            uint32_t ah[4][4], al[4][4];
            #pragma unroll
            for (int mf = 0; mf < 4; mf++) {
                int row = wm * 64 + mf * 16 + (lane & 7) + ((lane >> 3) & 1) * 8;
                int col = ks + (lane >> 4) * 8;
                uint32_t ad = aBase + (row * A_STR + col) * 2;
                ldmatrix_x4(ah[mf], ad);
                ldmatrix_x4(al[mf], ad + A_BYTES);
            }
            uint32_t bhf[4][2], blf[4][2];
            #pragma unroll
            for (int nh = 0; nh < 2; nh++) {
                int row = ks + ((lane >> 3) & 1) * 8 + (lane & 7);
                int col = wn * 32 + nh * 16 + (lane >> 4) * 8;
                uint32_t bd = bBase + (row * B_STR + col) * 2;
                uint32_t t4[4];
                ldmatrix_x4_trans(t4, bd);
                bhf[2 * nh][0] = t4[0]; bhf[2 * nh][1] = t4[1];
                bhf[2 * nh + 1][0] = t4[2]; bhf[2 * nh + 1][1] = t4[3];
                ldmatrix_x4_trans(t4, bd + B_BYTES);
                blf[2 * nh][0] = t4[0]; blf[2 * nh][1] = t4[1];
                blf[2 * nh + 1][0] = t4[2]; blf[2 * nh + 1][1] = t4[3];
            }
            #pragma unroll
            for (int mf = 0; mf < 4; mf++)
                #pragma unroll
                for (int nf = 0; nf < 4; nf++) {
                    mma16816(acc[mf][nf], ah[mf], bhf[nf]);
                    mma16816(acc[mf][nf], ah[mf], blf[nf]);
                    mma16816(acc[mf][nf], al[mf], bhf[nf]);
                }
        }

        if (t + 1 < NT) {
            store_a(buf ^ 1, pa);
            cp_wait0();
        }
        __syncthreads();
    }

    // ---- epilogue: Y[i,f] = d[i]*(acc + Xs[i,f]),  Xs = hi+lo (=d*X to 2^-22)
    float* Yb = Y + (size_t)b * NN * NF;
    #pragma unroll
    for (int mf = 0; mf < 4; mf++) {
        int row = m0 + wm * 64 + mf * 16 + (lane >> 2);
        float d0 = g_d[b * NN + row];
        float d1 = g_d[b * NN + row + 8];
        #pragma unroll
        for (int nf = 0; nf < 4; nf++) {
            int col = wn * 32 + nf * 8 + (lane & 3) * 2;
            float xs00 = __half2float(g_Xh[((size_t)b * NN + row) * DF + col])
                       + __half2float(g_Xl[((size_t)b * NN + row) * DF + col]);
            float xs01 = __half2float(g_Xh[((size_t)b * NN + row) * DF + col + 1])
                       + __half2float(g_Xl[((size_t)b * NN + row) * DF + col + 1]);
            float xs10 = __half2float(g_Xh[((size_t)b * NN + row + 8) * DF + col])
                       + __half2float(g_Xl[((size_t)b * NN + row + 8) * DF + col]);
            float xs11 = __half2float(g_Xh[((size_t)b * NN + row + 8) * DF + col + 1])
                       + __half2float(g_Xl[((size_t)b * NN + row + 8) * DF + col + 1]);
            float2 o0 = make_float2(d0 * (acc[mf][nf][0] + xs00),
                                    d0 * (acc[mf][nf][1] + xs01));
            float2 o1 = make_float2(d1 * (acc[mf][nf][2] + xs10),
                                    d1 * (acc[mf][nf][3] + xs11));
            *(float2*)&Yb[(size_t)row * NF + col] = o0;
            *(float2*)&Yb[(size_t)(row + 8) * NF + col] = o1;
        }
    }
}

// ---------------------------------------------------------------------------
// 5. H = relu(Y @ W)  [16384x128 @ 128x128] (fp32 SIMT)
// ---------------------------------------------------------------------------
#define BM 64
#define BK 32
__global__ __launch_bounds__(256) void k_gemm_YW(const float* __restrict__ W,
                                                 float* __restrict__ outH) {
    int m0 = blockIdx.x * BM;
    __shared__ float As[BM][BK + 1];
    __shared__ float Bs[BK][NF + 4];
    int tid = threadIdx.x;
    int tx  = tid & 31;
    int ty  = tid >> 5;

    float acc[8][4];
    #pragma unroll
    for (int r = 0; r < 8; r++)
        #pragma unroll
        for (int c = 0; c < 4; c++) acc[r][c] = 0.0f;

    for (int k0 = 0; k0 < DF; k0 += BK) {
        #pragma unroll
        for (int i = 0; i < 2; i++) {
            int idx = tid + i * 256;
            int r = idx >> 3;
            int cc = (idx & 7) << 2;
            float4 v = *(const float4*)&g_Y[(size_t)(m0 + r) * NF + k0 + cc];
            As[r][cc+0] = v.x; As[r][cc+1] = v.y; As[r][cc+2] = v.z; As[r][cc+3] = v.w;
        }
        #pragma unroll
        for (int i = 0; i < 4; i++) {
            int idx = tid + i * 256;
            int r = idx >> 5;
            int cc = (idx & 31) << 2;
            float4 v = *(const float4*)&W[(size_t)(k0 + r) * NF + cc];
            *(float4*)&Bs[r][cc] = v;
        }
        __syncthreads();
        #pragma unroll
        for (int kk = 0; kk < BK; kk++) {
            float a[8];
            #pragma unroll
            for (int r = 0; r < 8; r++) a[r] = As[ty * 8 + r][kk];
            float4 bv = *(const float4*)&Bs[kk][tx * 4];
            #pragma unroll
            for (int r = 0; r < 8; r++) {
                acc[r][0] += a[r] * bv.x;
                acc[r][1] += a[r] * bv.y;
                acc[r][2] += a[r] * bv.z;
                acc[r][3] += a[r] * bv.w;
            }
        }
        __syncthreads();
    }
    #pragma unroll
    for (int r = 0; r < 8; r++) {
        int i = m0 + ty * 8 + r;
        #pragma unroll
        for (int c = 0; c < 4; c++)
            outH[(size_t)i * NF + tx * 4 + c] = fmaxf(acc[r][c], 0.0f);
    }
}

// ---------------------------------------------------------------------------
extern "C" void kernel_launch(void* const* d_in, const int* in_sizes, int n_in,
                              void* d_out, int out_size) {
    const float* A = (const float*)d_in[0];
    const float* X = (const float*)d_in[1];
    const float* W = (const float*)d_in[2];

    float* outA = (float*)d_out;
    float* outH = (float*)d_out + (size_t)NB * NN * NN;

    static bool attr_set = false;
    if (!attr_set) {
        cudaFuncSetAttribute(k_mma, cudaFuncAttributeMaxDynamicSharedMemorySize, DYN_SMEM);
        attr_set = true;
    }

    float* Y;
    cudaGetSymbolAddress((void**)&Y, g_Y);

    k_zero<<<(NB * NN + 255) / 256, 256>>>();
    k_colsum<<<dim3(NN / 4 / 256, NN / 128, NB), 256>>>(A);
    k_dscale<<<(NB * NN * DF / 4) / 256, 256>>>(X);
    k_mma<<<dim3(NN / MT, NB), 256, DYN_SMEM>>>(A, outA, Y);
    k_gemm_YW<<<dim3(NB * NN / BM), 256>>>(W, outH);
}

// round 9
// speedup vs baseline: 1.2894x; 1.2894x over previous
#include <cuda_runtime.h>
#include <cuda_fp16.h>
#include <cstdint>

#define NB 8
#define NN 2048
#define DF 128
#define NF 128

// ---------------- scratch (device globals; no allocation allowed) ----------
__device__ float  g_colsum[NB * NN];
__device__ float  g_d[NB * NN];
__device__ __half g_Xs16[NB * NN * DF];  // fp16 of Xs = d*X, natural [b][j][f]
__device__ float  g_Y[NB * NN * NF];

// ---------------- helpers ---------------------------------------------------
__device__ __forceinline__ uint32_t smem_u32(const void* p) {
    uint32_t a;
    asm("{ .reg .u64 t; cvta.to.shared.u64 t, %1; cvt.u32.u64 %0, t; }"
        : "=r"(a) : "l"(p));
    return a;
}
__device__ __forceinline__ void ldmatrix_x4(uint32_t* r, uint32_t addr) {
    asm volatile("ldmatrix.sync.aligned.m8n8.x4.shared.b16 {%0,%1,%2,%3}, [%4];"
                 : "=r"(r[0]), "=r"(r[1]), "=r"(r[2]), "=r"(r[3]) : "r"(addr));
}
__device__ __forceinline__ void ldmatrix_x4_trans(uint32_t* r, uint32_t addr) {
    asm volatile("ldmatrix.sync.aligned.m8n8.x4.trans.shared.b16 {%0,%1,%2,%3}, [%4];"
                 : "=r"(r[0]), "=r"(r[1]), "=r"(r[2]), "=r"(r[3]) : "r"(addr));
}
__device__ __forceinline__ void mma16816(float* d, const uint32_t* a, const uint32_t* b) {
    asm volatile(
        "mma.sync.aligned.m16n8k16.row.col.f32.f16.f16.f32 "
        "{%0,%1,%2,%3}, {%4,%5,%6,%7}, {%8,%9}, {%0,%1,%2,%3};"
        : "+f"(d[0]), "+f"(d[1]), "+f"(d[2]), "+f"(d[3])
        : "r"(a[0]), "r"(a[1]), "r"(a[2]), "r"(a[3]), "r"(b[0]), "r"(b[1]));
}

// ---------------------------------------------------------------------------
// 1. zero colsum accumulator
// ---------------------------------------------------------------------------
__global__ void k_zero() {
    int i = blockIdx.x * blockDim.x + threadIdx.x;
    if (i < NB * NN) g_colsum[i] = 0.0f;
}

// ---------------------------------------------------------------------------
// 2. fused copy A->out + column sums (float4 vectorized)
// ---------------------------------------------------------------------------
__global__ __launch_bounds__(256) void k_copy_colsum(const float* __restrict__ A,
                                                     float* __restrict__ outA) {
    int b  = blockIdx.z;
    int c4 = blockIdx.x * 256 + threadIdx.x;
    int r0 = blockIdx.y * 128;
    const float4* Ab = (const float4*)(A    + (size_t)b * NN * NN) + c4;
    float4*       Ob = (float4*)      (outA + (size_t)b * NN * NN) + c4;
    float4 s = make_float4(0.f, 0.f, 0.f, 0.f);
    #pragma unroll 4
    for (int r = 0; r < 128; r++) {
        float4 v = Ab[(size_t)(r0 + r) * (NN / 4)];
        Ob[(size_t)(r0 + r) * (NN / 4)] = v;
        s.x += v.x; s.y += v.y; s.z += v.z; s.w += v.w;
    }
    float* cs = &g_colsum[b * NN + c4 * 4];
    atomicAdd(cs + 0, s.x);
    atomicAdd(cs + 1, s.y);
    atomicAdd(cs + 2, s.z);
    atomicAdd(cs + 3, s.w);
}

// ---------------------------------------------------------------------------
// 3. d = rsqrt(colsum+1); Xs16 = fp16(d*X)  (natural layout)
// ---------------------------------------------------------------------------
__global__ __launch_bounds__(256) void k_dscale(const float* __restrict__ X) {
    int q   = blockIdx.x * 256 + threadIdx.x;          // float4 index
    int row = q >> 5;                                  // 32 float4 per row
    float dv = rsqrtf(g_colsum[row] + 1.0f);
    if ((q & 31) == 0) g_d[row] = dv;
    float4 v = ((const float4*)X)[q];
    __half2 h01 = __floats2half2_rn(dv * v.x, dv * v.y);
    __half2 h23 = __floats2half2_rn(dv * v.z, dv * v.w);
    uint2 hv = make_uint2(*(uint32_t*)&h01, *(uint32_t*)&h23);
    *(uint2*)&g_Xs16[q * 4] = hv;
}

// ---------------------------------------------------------------------------
// 4. HMMA GEMM (single fp16): acc = A16 @ Xs16, fp32 accumulate.
//    CTA: 128x128 tile, K-tile 32, 8 warps (2x4), double-buffered smem.
//    Epilogue: Y[i,f] = d[i]*acc + d[i]^2*X[i,f]  (self-loop exact in fp32)
// ---------------------------------------------------------------------------
#define KT 32
#define A_STR 40            // halves per A-tile row (pad 8 -> conflict-free ldmatrix)
#define B_STR 136           // halves per B-tile row (pad 8 -> conflict-free trans)
#define A_BYTES (128 * A_STR * 2)     // 10240
#define B_BYTES (KT * B_STR * 2)      // 8704
#define BUF_BYTES (A_BYTES + B_BYTES) // 18944
#define DYN_SMEM (2 * BUF_BYTES)      // 37888

__global__ __launch_bounds__(256, 1) void k_mma(const float* __restrict__ A,
                                                const float* __restrict__ X,
                                                float* __restrict__ Y) {
    extern __shared__ char smem[];
    int tid  = threadIdx.x;
    int wid  = tid >> 5;
    int lane = tid & 31;
    int wm   = wid >> 2;        // 0..1 (64 rows each)
    int wn   = wid & 3;         // 0..3 (32 cols each)
    int b    = blockIdx.y;
    int m0   = blockIdx.x * 128;

    const float*  Ab  = A + (size_t)b * NN * NN + (size_t)m0 * NN;
    const __half* BG  = g_Xs16 + (size_t)b * NN * DF;

    float acc[4][4][4];
    #pragma unroll
    for (int i = 0; i < 4; i++)
        #pragma unroll
        for (int j = 0; j < 4; j++)
            #pragma unroll
            for (int c = 0; c < 4; c++) acc[i][j][c] = 0.0f;

    auto a_p = [&](int buf) { return smem + buf * BUF_BYTES; };
    auto b_p = [&](int buf) { return smem + buf * BUF_BYTES + A_BYTES; };

    // per-thread load coordinates
    //   A: 4 float4/thread; q = tid + i*256; row=q>>3 (8 quads/row), c4=q&7
    //   B: 2 uint4/thread;  q = tid + i*256; row=q>>4 (16 per row), u=q&15
    auto store_tile = [&](int buf, const float4* pa, const uint4* pb) {
        char* ap = a_p(buf);
        char* bp = b_p(buf);
        #pragma unroll
        for (int i = 0; i < 4; i++) {
            int q = tid + i * 256, row = q >> 3, c4 = q & 7;
            __half2 h01 = __floats2half2_rn(pa[i].x, pa[i].y);
            __half2 h23 = __floats2half2_rn(pa[i].z, pa[i].w);
            uint2 hv = make_uint2(*(uint32_t*)&h01, *(uint32_t*)&h23);
            int off = (row * A_STR + c4 * 4) * 2;
            *(uint2*)(ap + off) = hv;
        }
        #pragma unroll
        for (int i = 0; i < 2; i++) {
            int q = tid + i * 256, row = q >> 4, u = q & 15;
            int off = (row * B_STR + u * 8) * 2;
            *(uint4*)(bp + off) = pb[i];
        }
    };
    auto load_tile_g = [&](int t, float4* pa, uint4* pb) {
        int k0 = t * KT;
        #pragma unroll
        for (int i = 0; i < 4; i++) {
            int q = tid + i * 256, row = q >> 3, c4 = q & 7;
            pa[i] = *(const float4*)(Ab + (size_t)row * NN + k0 + c4 * 4);
        }
        #pragma unroll
        for (int i = 0; i < 2; i++) {
            int q = tid + i * 256, row = q >> 4, u = q & 15;
            pb[i] = *(const uint4*)(BG + (size_t)(k0 + row) * DF + u * 8);
        }
    };

    {   // prologue: tile 0
        float4 pa[4]; uint4 pb[2];
        load_tile_g(0, pa, pb);
        store_tile(0, pa, pb);
    }
    __syncthreads();

    const int NT = NN / KT;     // 64
    for (int t = 0; t < NT; t++) {
        int buf = t & 1;
        float4 pa[4]; uint4 pb[2];
        if (t + 1 < NT) load_tile_g(t + 1, pa, pb);

        // ---- compute on buf ----
        uint32_t aBase = smem_u32(a_p(buf));
        uint32_t bBase = smem_u32(b_p(buf));
        #pragma unroll
        for (int ks = 0; ks < KT; ks += 16) {
            uint32_t af[4][4];
            #pragma unroll
            for (int mf = 0; mf < 4; mf++) {
                int row = wm * 64 + mf * 16 + (lane & 7) + ((lane >> 3) & 1) * 8;
                int col = ks + (lane >> 4) * 8;
                ldmatrix_x4(af[mf], aBase + (row * A_STR + col) * 2);
            }
            uint32_t bf[4][2];
            #pragma unroll
            for (int nh = 0; nh < 2; nh++) {
                int row = ks + ((lane >> 3) & 1) * 8 + (lane & 7);
                int col = wn * 32 + nh * 16 + (lane >> 4) * 8;
                uint32_t t4[4];
                ldmatrix_x4_trans(t4, bBase + (row * B_STR + col) * 2);
                bf[2 * nh][0] = t4[0]; bf[2 * nh][1] = t4[1];
                bf[2 * nh + 1][0] = t4[2]; bf[2 * nh + 1][1] = t4[3];
            }
            #pragma unroll
            for (int mf = 0; mf < 4; mf++)
                #pragma unroll
                for (int nf = 0; nf < 4; nf++)
                    mma16816(acc[mf][nf], af[mf], bf[nf]);
        }

        if (t + 1 < NT) store_tile(buf ^ 1, pa, pb);
        __syncthreads();
    }

    // ---- epilogue: Y[i,f] = d[i]*acc + d[i]^2*X[i,f]  (fp32 self-loop) ----
    float* Yb = Y + (size_t)b * NN * NF;
    const float* Xb = X + (size_t)b * NN * DF;
    #pragma unroll
    for (int mf = 0; mf < 4; mf++) {
        int row = m0 + wm * 64 + mf * 16 + (lane >> 2);
        float d0 = g_d[b * NN + row];
        float d1 = g_d[b * NN + row + 8];
        float e0 = d0 * d0, e1 = d1 * d1;
        #pragma unroll
        for (int nf = 0; nf < 4; nf++) {
            int col = wn * 32 + nf * 8 + (lane & 3) * 2;
            float2 x0 = *(const float2*)&Xb[(size_t)row * DF + col];
            float2 x1 = *(const float2*)&Xb[(size_t)(row + 8) * DF + col];
            float2 o0 = make_float2(d0 * acc[mf][nf][0] + e0 * x0.x,
                                    d0 * acc[mf][nf][1] + e0 * x0.y);
            float2 o1 = make_float2(d1 * acc[mf][nf][2] + e1 * x1.x,
                                    d1 * acc[mf][nf][3] + e1 * x1.y);
            *(float2*)&Yb[(size_t)row * NF + col] = o0;
            *(float2*)&Yb[(size_t)(row + 8) * NF + col] = o1;
        }
    }
}

// ---------------------------------------------------------------------------
// 5. H = relu(Y @ W)  [16384x128 @ 128x128] (fp32 SIMT)
// ---------------------------------------------------------------------------
#define BM 64
#define BK 32
__global__ __launch_bounds__(256) void k_gemm_YW(const float* __restrict__ W,
                                                 float* __restrict__ outH) {
    int m0 = blockIdx.x * BM;
    __shared__ float As[BM][BK + 1];
    __shared__ float Bs[BK][NF + 4];
    int tid = threadIdx.x;
    int tx  = tid & 31;
    int ty  = tid >> 5;

    float acc[8][4];
    #pragma unroll
    for (int r = 0; r < 8; r++)
        #pragma unroll
        for (int c = 0; c < 4; c++) acc[r][c] = 0.0f;

    for (int k0 = 0; k0 < DF; k0 += BK) {
        #pragma unroll
        for (int i = 0; i < 2; i++) {
            int idx = tid + i * 256;
            int r = idx >> 3;
            int cc = (idx & 7) << 2;
            float4 v = *(const float4*)&g_Y[(size_t)(m0 + r) * NF + k0 + cc];
            As[r][cc+0] = v.x; As[r][cc+1] = v.y; As[r][cc+2] = v.z; As[r][cc+3] = v.w;
        }
        #pragma unroll
        for (int i = 0; i < 4; i++) {
            int idx = tid + i * 256;
            int r = idx >> 5;
            int cc = (idx & 31) << 2;
            float4 v = *(const float4*)&W[(size_t)(k0 + r) * NF + cc];
            *(float4*)&Bs[r][cc] = v;
        }
        __syncthreads();
        #pragma unroll
        for (int kk = 0; kk < BK; kk++) {
            float a[8];
            #pragma unroll
            for (int r = 0; r < 8; r++) a[r] = As[ty * 8 + r][kk];
            float4 bv = *(const float4*)&Bs[kk][tx * 4];
            #pragma unroll
            for (int r = 0; r < 8; r++) {
                acc[r][0] += a[r] * bv.x;
                acc[r][1] += a[r] * bv.y;
                acc[r][2] += a[r] * bv.z;
                acc[r][3] += a[r] * bv.w;
            }
        }
        __syncthreads();
    }
    #pragma unroll
    for (int r = 0; r < 8; r++) {
        int i = m0 + ty * 8 + r;
        #pragma unroll
        for (int c = 0; c < 4; c++)
            outH[(size_t)i * NF + tx * 4 + c] = fmaxf(acc[r][c], 0.0f);
    }
}

// ---------------------------------------------------------------------------
extern "C" void kernel_launch(void* const* d_in, const int* in_sizes, int n_in,
                              void* d_out, int out_size) {
    const float* A = (const float*)d_in[0];
    const float* X = (const float*)d_in[1];
    const float* W = (const float*)d_in[2];

    float* outA = (float*)d_out;
    float* outH = (float*)d_out + (size_t)NB * NN * NN;

    static bool attr_set = false;
    if (!attr_set) {
        cudaFuncSetAttribute(k_mma, cudaFuncAttributeMaxDynamicSharedMemorySize, DYN_SMEM);
        attr_set = true;
    }

    float* Y;
    cudaGetSymbolAddress((void**)&Y, g_Y);

    k_zero<<<(NB * NN + 255) / 256, 256>>>();
    k_copy_colsum<<<dim3(NN / 4 / 256, NN / 128, NB), 256>>>(A, outA);
    k_dscale<<<(NB * NN * DF / 4) / 256, 256>>>(X);
    k_mma<<<dim3(NN / 128, NB), 256, DYN_SMEM>>>(A, X, Y);
    k_gemm_YW<<<dim3(NB * NN / BM), 256>>>(W, outH);
}

// round 10
// speedup vs baseline: 1.5522x; 1.2038x over previous
#include <cuda_runtime.h>
#include <cuda_fp16.h>
#include <cstdint>

#define NB 8
#define NN 2048
#define DF 128
#define NF 128

// ---------------- scratch (device globals; no allocation allowed) ----------
__device__ float  g_colsum[NB * NN];
__device__ float  g_d[NB * NN];
__device__ __half g_A16[(size_t)NB * NN * NN];  // fp16 cast of A
__device__ __half g_Xs16[NB * NN * DF];         // fp16 of Xs = d*X, [b][j][f]
__device__ __half g_W16[DF * NF];               // fp16 of W
__device__ __half g_Y16[NB * NN * NF];          // fp16 of Y (input to YW GEMM)

// ---------------- helpers ---------------------------------------------------
__device__ __forceinline__ uint32_t smem_u32(const void* p) {
    uint32_t a;
    asm("{ .reg .u64 t; cvta.to.shared.u64 t, %1; cvt.u32.u64 %0, t; }"
        : "=r"(a) : "l"(p));
    return a;
}
__device__ __forceinline__ void ldmatrix_x4(uint32_t* r, uint32_t addr) {
    asm volatile("ldmatrix.sync.aligned.m8n8.x4.shared.b16 {%0,%1,%2,%3}, [%4];"
                 : "=r"(r[0]), "=r"(r[1]), "=r"(r[2]), "=r"(r[3]) : "r"(addr));
}
__device__ __forceinline__ void ldmatrix_x4_trans(uint32_t* r, uint32_t addr) {
    asm volatile("ldmatrix.sync.aligned.m8n8.x4.trans.shared.b16 {%0,%1,%2,%3}, [%4];"
                 : "=r"(r[0]), "=r"(r[1]), "=r"(r[2]), "=r"(r[3]) : "r"(addr));
}
__device__ __forceinline__ void mma16816(float* d, const uint32_t* a, const uint32_t* b) {
    asm volatile(
        "mma.sync.aligned.m16n8k16.row.col.f32.f16.f16.f32 "
        "{%0,%1,%2,%3}, {%4,%5,%6,%7}, {%8,%9}, {%0,%1,%2,%3};"
        : "+f"(d[0]), "+f"(d[1]), "+f"(d[2]), "+f"(d[3])
        : "r"(a[0]), "r"(a[1]), "r"(a[2]), "r"(a[3]), "r"(b[0]), "r"(b[1]));
}
__device__ __forceinline__ void cp_async16(uint32_t saddr, const void* gaddr) {
    asm volatile("cp.async.cg.shared.global [%0], [%1], 16;"
                 :: "r"(saddr), "l"(gaddr) : "memory");
}
__device__ __forceinline__ void cp_commit() {
    asm volatile("cp.async.commit_group;" ::: "memory");
}

// ---------------------------------------------------------------------------
// 1. zero colsum accumulator
// ---------------------------------------------------------------------------
__global__ void k_zero() {
    int i = blockIdx.x * blockDim.x + threadIdx.x;
    if (i < NB * NN) g_colsum[i] = 0.0f;
}

// ---------------------------------------------------------------------------
// 2. fused: copy A -> outA, emit A16 = fp16(A), column sums
// ---------------------------------------------------------------------------
__global__ __launch_bounds__(256) void k_copy_colsum(const float* __restrict__ A,
                                                     float* __restrict__ outA) {
    int b  = blockIdx.z;
    int c4 = blockIdx.x * 256 + threadIdx.x;
    int r0 = blockIdx.y * 128;
    const float4* Ab = (const float4*)(A    + (size_t)b * NN * NN) + c4;
    float4*       Ob = (float4*)      (outA + (size_t)b * NN * NN) + c4;
    __half*       Hb = g_A16 + (size_t)b * NN * NN;
    float4 s = make_float4(0.f, 0.f, 0.f, 0.f);
    #pragma unroll 4
    for (int r = 0; r < 128; r++) {
        float4 v = Ab[(size_t)(r0 + r) * (NN / 4)];
        Ob[(size_t)(r0 + r) * (NN / 4)] = v;
        __half2 h01 = __floats2half2_rn(v.x, v.y);
        __half2 h23 = __floats2half2_rn(v.z, v.w);
        *(uint2*)&Hb[(size_t)(r0 + r) * NN + c4 * 4] =
            make_uint2(*(uint32_t*)&h01, *(uint32_t*)&h23);
        s.x += v.x; s.y += v.y; s.z += v.z; s.w += v.w;
    }
    float* cs = &g_colsum[b * NN + c4 * 4];
    atomicAdd(cs + 0, s.x);
    atomicAdd(cs + 1, s.y);
    atomicAdd(cs + 2, s.z);
    atomicAdd(cs + 3, s.w);
}

// ---------------------------------------------------------------------------
// 3. d = rsqrt(colsum+1); Xs16 = fp16(d*X)
// ---------------------------------------------------------------------------
__global__ __launch_bounds__(256) void k_dscale(const float* __restrict__ X) {
    int q   = blockIdx.x * 256 + threadIdx.x;          // float4 index
    int row = q >> 5;                                  // 32 float4 per row
    float dv = rsqrtf(g_colsum[row] + 1.0f);
    if ((q & 31) == 0) g_d[row] = dv;
    float4 v = ((const float4*)X)[q];
    __half2 h01 = __floats2half2_rn(dv * v.x, dv * v.y);
    __half2 h23 = __floats2half2_rn(dv * v.z, dv * v.w);
    *(uint2*)&g_Xs16[q * 4] = make_uint2(*(uint32_t*)&h01, *(uint32_t*)&h23);
}

// ---------------------------------------------------------------------------
// 3b. W -> fp16
// ---------------------------------------------------------------------------
__global__ void k_convW(const float* __restrict__ W) {
    int q = blockIdx.x * 256 + threadIdx.x;           // float4 index, 4096 total
    float4 v = ((const float4*)W)[q];
    __half2 h01 = __floats2half2_rn(v.x, v.y);
    __half2 h23 = __floats2half2_rn(v.z, v.w);
    *(uint2*)&g_W16[q * 4] = make_uint2(*(uint32_t*)&h01, *(uint32_t*)&h23);
}

// ---------------------------------------------------------------------------
// 4. HMMA GEMM: acc = A16 @ Xs16, 128x128 CTA tile, KT=32, 8 warps (2x4),
//    4-stage cp.async pipeline (both operands fp16 in gmem).
//    Epilogue: Y16[i,f] = fp16(d[i]*acc + d[i]^2*X[i,f])
// ---------------------------------------------------------------------------
#define KT 32
#define NSTAGE 4
#define A_STR 40            // halves per A-tile row (pad 8)
#define B_STR 136           // halves per B-tile row (pad 8)
#define A_BYTES (128 * A_STR * 2)     // 10240
#define B_BYTES (KT * B_STR * 2)      // 8704
#define STG_BYTES (A_BYTES + B_BYTES) // 18944
#define DYN_SMEM (NSTAGE * STG_BYTES) // 75776

__global__ __launch_bounds__(256, 1) void k_mma(const float* __restrict__ X) {
    extern __shared__ char smem[];
    int tid  = threadIdx.x;
    int wid  = tid >> 5;
    int lane = tid & 31;
    int wm   = wid >> 2;        // 0..1 (64 rows each)
    int wn   = wid & 3;         // 0..3 (32 cols each)
    int b    = blockIdx.y;
    int m0   = blockIdx.x * 128;

    const __half* AG = g_A16  + (size_t)b * NN * NN + (size_t)m0 * NN;
    const __half* BG = g_Xs16 + (size_t)b * NN * DF;

    float acc[4][4][4];
    #pragma unroll
    for (int i = 0; i < 4; i++)
        #pragma unroll
        for (int j = 0; j < 4; j++)
            #pragma unroll
            for (int c = 0; c < 4; c++) acc[i][j][c] = 0.0f;

    uint32_t sb = smem_u32(smem);

    // issue tile t into stage s:
    //   A: 512 16B chunks (2/thread): q=tid+i*256, row=q>>2, c=q&3
    //   B: 512 16B chunks (2/thread): q=tid+i*256, row=q>>4, u=q&15
    auto issue = [&](int t, int s) {
        int k0 = t * KT;
        uint32_t ap = sb + s * STG_BYTES;
        uint32_t bp = ap + A_BYTES;
        #pragma unroll
        for (int i = 0; i < 2; i++) {
            int q = tid + i * 256, row = q >> 2, c = q & 3;
            cp_async16(ap + (uint32_t)(row * A_STR + c * 8) * 2,
                       AG + (size_t)row * NN + k0 + c * 8);
        }
        #pragma unroll
        for (int i = 0; i < 2; i++) {
            int q = tid + i * 256, row = q >> 4, u = q & 15;
            cp_async16(bp + (uint32_t)(row * B_STR + u * 8) * 2,
                       BG + (size_t)(k0 + row) * DF + u * 8);
        }
        cp_commit();
    };

    // prologue: stages 0..NSTAGE-2
    #pragma unroll
    for (int s = 0; s < NSTAGE - 1; s++) issue(s, s);

    const int NT = NN / KT;     // 64
    for (int t = 0; t < NT; t++) {
        asm volatile("cp.async.wait_group %0;" :: "n"(NSTAGE - 2) : "memory");
        __syncthreads();
        if (t + NSTAGE - 1 < NT) issue(t + NSTAGE - 1, (t + NSTAGE - 1) % NSTAGE);
        else cp_commit();       // keep group accounting uniform

        int s = t % NSTAGE;
        uint32_t aBase = sb + s * STG_BYTES;
        uint32_t bBase = aBase + A_BYTES;
        #pragma unroll
        for (int ks = 0; ks < KT; ks += 16) {
            uint32_t af[4][4];
            #pragma unroll
            for (int mf = 0; mf < 4; mf++) {
                int row = wm * 64 + mf * 16 + (lane & 7) + ((lane >> 3) & 1) * 8;
                int col = ks + (lane >> 4) * 8;
                ldmatrix_x4(af[mf], aBase + (row * A_STR + col) * 2);
            }
            uint32_t bf[4][2];
            #pragma unroll
            for (int nh = 0; nh < 2; nh++) {
                int row = ks + ((lane >> 3) & 1) * 8 + (lane & 7);
                int col = wn * 32 + nh * 16 + (lane >> 4) * 8;
                uint32_t t4[4];
                ldmatrix_x4_trans(t4, bBase + (row * B_STR + col) * 2);
                bf[2 * nh][0] = t4[0]; bf[2 * nh][1] = t4[1];
                bf[2 * nh + 1][0] = t4[2]; bf[2 * nh + 1][1] = t4[3];
            }
            #pragma unroll
            for (int mf = 0; mf < 4; mf++)
                #pragma unroll
                for (int nf = 0; nf < 4; nf++)
                    mma16816(acc[mf][nf], af[mf], bf[nf]);
        }
        __syncthreads();
    }

    // ---- epilogue: Y16[i,f] = fp16(d[i]*acc + d[i]^2*X[i,f]) ----
    __half* Yb = g_Y16 + (size_t)b * NN * NF;
    const float* Xb = X + (size_t)b * NN * DF;
    #pragma unroll
    for (int mf = 0; mf < 4; mf++) {
        int row = m0 + wm * 64 + mf * 16 + (lane >> 2);
        float d0 = g_d[b * NN + row];
        float d1 = g_d[b * NN + row + 8];
        float e0 = d0 * d0, e1 = d1 * d1;
        #pragma unroll
        for (int nf = 0; nf < 4; nf++) {
            int col = wn * 32 + nf * 8 + (lane & 3) * 2;
            float2 x0 = *(const float2*)&Xb[(size_t)row * DF + col];
            float2 x1 = *(const float2*)&Xb[(size_t)(row + 8) * DF + col];
            __half2 o0 = __floats2half2_rn(d0 * acc[mf][nf][0] + e0 * x0.x,
                                           d0 * acc[mf][nf][1] + e0 * x0.y);
            __half2 o1 = __floats2half2_rn(d1 * acc[mf][nf][2] + e1 * x1.x,
                                           d1 * acc[mf][nf][3] + e1 * x1.y);
            *(__half2*)&Yb[(size_t)row * NF + col] = o0;
            *(__half2*)&Yb[(size_t)(row + 8) * NF + col] = o1;
        }
    }
}

// ---------------------------------------------------------------------------
// 5. H = relu(Y16 @ W16)  [16384x128 @ 128x128], HMMA, one-shot smem tiles.
// ---------------------------------------------------------------------------
#define YW_STR 136
#define YT_BYTES (128 * YW_STR * 2)   // 34816
#define YW_SMEM (2 * YT_BYTES)        // 69632

__global__ __launch_bounds__(256, 1) void k_gemm_YW(float* __restrict__ outH) {
    extern __shared__ char smem[];
    int tid  = threadIdx.x;
    int wid  = tid >> 5;
    int lane = tid & 31;
    int wm   = wid >> 2;
    int wn   = wid & 3;
    int m0   = blockIdx.x * 128;

    char* yt = smem;              // 128 rows x 128 cols (k) fp16, stride YW_STR
    char* wt = smem + YT_BYTES;   // 128 rows (k) x 128 cols (n) fp16

    // load tiles: 2048 halves8-chunks... 128*128 halves = 2048 uint4 total per tile,
    // 8 per thread
    #pragma unroll
    for (int i = 0; i < 8; i++) {
        int q = tid + i * 256, row = q >> 4, u = q & 15;
        *(uint4*)(yt + (row * YW_STR + u * 8) * 2) =
            *(const uint4*)&g_Y16[(size_t)(m0 + row) * NF + u * 8];
        *(uint4*)(wt + (row * YW_STR + u * 8) * 2) =
            *(const uint4*)&g_W16[row * NF + u * 8];
    }
    __syncthreads();

    float acc[4][4][4];
    #pragma unroll
    for (int i = 0; i < 4; i++)
        #pragma unroll
        for (int j = 0; j < 4; j++)
            #pragma unroll
            for (int c = 0; c < 4; c++) acc[i][j][c] = 0.0f;

    uint32_t yBase = smem_u32(yt);
    uint32_t wBase = smem_u32(wt);
    #pragma unroll
    for (int ks = 0; ks < DF; ks += 16) {
        uint32_t af[4][4];
        #pragma unroll
        for (int mf = 0; mf < 4; mf++) {
            int row = wm * 64 + mf * 16 + (lane & 7) + ((lane >> 3) & 1) * 8;
            int col = ks + (lane >> 4) * 8;
            ldmatrix_x4(af[mf], yBase + (row * YW_STR + col) * 2);
        }
        uint32_t bf[4][2];
        #pragma unroll
        for (int nh = 0; nh < 2; nh++) {
            int row = ks + ((lane >> 3) & 1) * 8 + (lane & 7);
            int col = wn * 32 + nh * 16 + (lane >> 4) * 8;
            uint32_t t4[4];
            ldmatrix_x4_trans(t4, wBase + (row * YW_STR + col) * 2);
            bf[2 * nh][0] = t4[0]; bf[2 * nh][1] = t4[1];
            bf[2 * nh + 1][0] = t4[2]; bf[2 * nh + 1][1] = t4[3];
        }
        #pragma unroll
        for (int mf = 0; mf < 4; mf++)
            #pragma unroll
            for (int nf = 0; nf < 4; nf++)
                mma16816(acc[mf][nf], af[mf], bf[nf]);
    }

    #pragma unroll
    for (int mf = 0; mf < 4; mf++) {
        int row = m0 + wm * 64 + mf * 16 + (lane >> 2);
        #pragma unroll
        for (int nf = 0; nf < 4; nf++) {
            int col = wn * 32 + nf * 8 + (lane & 3) * 2;
            float2 o0 = make_float2(fmaxf(acc[mf][nf][0], 0.f),
                                    fmaxf(acc[mf][nf][1], 0.f));
            float2 o1 = make_float2(fmaxf(acc[mf][nf][2], 0.f),
                                    fmaxf(acc[mf][nf][3], 0.f));
            *(float2*)&outH[(size_t)row * NF + col] = o0;
            *(float2*)&outH[(size_t)(row + 8) * NF + col] = o1;
        }
    }
}

// ---------------------------------------------------------------------------
extern "C" void kernel_launch(void* const* d_in, const int* in_sizes, int n_in,
                              void* d_out, int out_size) {
    const float* A = (const float*)d_in[0];
    const float* X = (const float*)d_in[1];
    const float* W = (const float*)d_in[2];

    float* outA = (float*)d_out;
    float* outH = (float*)d_out + (size_t)NB * NN * NN;

    static bool attr_set = false;
    if (!attr_set) {
        cudaFuncSetAttribute(k_mma, cudaFuncAttributeMaxDynamicSharedMemorySize, DYN_SMEM);
        cudaFuncSetAttribute(k_gemm_YW, cudaFuncAttributeMaxDynamicSharedMemorySize, YW_SMEM);
        attr_set = true;
    }

    k_zero<<<(NB * NN + 255) / 256, 256>>>();
    k_copy_colsum<<<dim3(NN / 4 / 256, NN / 128, NB), 256>>>(A, outA);
    k_dscale<<<(NB * NN * DF / 4) / 256, 256>>>(X);
    k_convW<<<(DF * NF / 4) / 256, 256>>>(W);
    k_mma<<<dim3(NN / 128, NB), 256, DYN_SMEM>>>(X);
    k_gemm_YW<<<NB * NN / 128, 256, YW_SMEM>>>(outH);
}